// round 15
// baseline (speedup 1.0000x reference)
#include <cuda_runtime.h>
#include <cuda_fp16.h>
#include <math.h>
#include <stdint.h>

// Problem constants
constexpr int B_ = 4, S_ = 4096, D_ = 64;
constexpr int MT = 64;            // q rows per tile (one phase)
constexpr int NT = 128;           // keys per k-tile
constexpr float QSCALE = 0.18033688011112042f;  // 0.125 * log2(e), folded into Q

// ---- global scratch (allocation-free rule) ----
__device__ __align__(16) __half g_Qh[B_*S_*D_];
__device__ __align__(16) __half g_Kh[B_*S_*D_];   // zeroed on padded keys
__device__ __align__(16) __half g_Vh[B_*S_*D_];   // zeroed on padded keys
__device__ __align__(16) __half g_pad1h[B_*S_];   // 1.0 keep / 0.0 masked
__device__ float g_part[128][D_];                 // V_p column sums per proj CTA

__device__ __forceinline__ uint32_t smem_u32(const void* p) {
    uint32_t a;
    asm("{ .reg .u64 t; cvta.to.shared.u64 t, %1; cvt.u32.u64 %0, t; }" : "=r"(a) : "l"(p));
    return a;
}

// ---- mma.sync / ldmatrix / misc PTX ----
__device__ __forceinline__ void ldm_x4(uint32_t* r, uint32_t a) {
    asm volatile("ldmatrix.sync.aligned.m8n8.x4.shared.b16 {%0,%1,%2,%3}, [%4];"
                 : "=r"(r[0]), "=r"(r[1]), "=r"(r[2]), "=r"(r[3]) : "r"(a));
}
__device__ __forceinline__ void ldm_x4_t(uint32_t* r, uint32_t a) {
    asm volatile("ldmatrix.sync.aligned.m8n8.x4.trans.shared.b16 {%0,%1,%2,%3}, [%4];"
                 : "=r"(r[0]), "=r"(r[1]), "=r"(r[2]), "=r"(r[3]) : "r"(a));
}
__device__ __forceinline__ void mma_f16(float* c, const uint32_t* a, const uint32_t* b) {
    asm volatile("mma.sync.aligned.m16n8k16.row.col.f32.f16.f16.f32 "
                 "{%0,%1,%2,%3}, {%4,%5,%6,%7}, {%8,%9}, {%0,%1,%2,%3};"
                 : "+f"(c[0]), "+f"(c[1]), "+f"(c[2]), "+f"(c[3])
                 : "r"(a[0]), "r"(a[1]), "r"(a[2]), "r"(a[3]), "r"(b[0]), "r"(b[1]));
}
__device__ __forceinline__ float ex2(float x) {
    float y; asm("ex2.approx.f32 %0, %1;" : "=f"(y) : "f"(x)); return y;
}
// pack two fp32 -> fp16x2; second arg lands in the LOW half
__device__ __forceinline__ uint32_t cvt_f16x2(float hi, float lo) {
    uint32_t r; asm("cvt.rn.f16x2.f32 %0, %1, %2;" : "=r"(r) : "f"(hi), "f"(lo)); return r;
}
__device__ __forceinline__ uint32_t lds32(uint32_t a) {
    uint32_t v; asm volatile("ld.shared.b32 %0, [%1];" : "=r"(v) : "r"(a)); return v;
}
__device__ __forceinline__ void sts128(uint32_t a, uint32_t x, uint32_t y, uint32_t z, uint32_t w) {
    asm volatile("st.shared.v4.b32 [%0], {%1,%2,%3,%4};"
                 :: "r"(a), "r"(x), "r"(y), "r"(z), "r"(w) : "memory");
}
__device__ __forceinline__ void cpa16(uint32_t dst, const void* src) {
    asm volatile("cp.async.cg.shared.global [%0], [%1], 16;" :: "r"(dst), "l"(src));
}
__device__ __forceinline__ void pref_l2(const void* p) {
    asm volatile("prefetch.global.L2 [%0];" :: "l"(p));
}
#define CP_COMMIT() asm volatile("cp.async.commit_group;" ::: "memory")
#define CP_WAIT0()  asm volatile("cp.async.wait_group 0;" ::: "memory")

// ---------------------------------------------------------------------------
// Kernel 1: tensor-core QKV projection (round-13 core + PK/PV L2 prefetch).
// D = E @ W^T emulated in fp32 precision by fp16 hi/lo (3 combos).
// Also: pad dtype detect + canonical half mask, padded-K/V zeroing, and
// per-CTA fp32 V_p column sums (meanV). 128 CTAs x 256 threads.
// ---------------------------------------------------------------------------
constexpr int PSE_HI = 0;                       // E hi: 128 x 128B (swizzled)
constexpr int PSE_LO = 16384;                   // E lo
constexpr int PSW    = 32768;                   // W: 3 x (hi 8KB + lo 8KB)
constexpr int PROJ_SMEM = PSW + 3 * 16384;      // 81920

__global__ __launch_bounds__(256) void proj_kernel(
    const float* __restrict__ E,  const float* __restrict__ PK, const float* __restrict__ PV,
    const float* __restrict__ Wq, const float* __restrict__ bq,
    const float* __restrict__ Wk, const float* __restrict__ bk,
    const float* __restrict__ Wv, const float* __restrict__ bv,
    const void* __restrict__ pad)
{
    extern __shared__ char psm[];
    const uint32_t smb = smem_u32(psm);
    __shared__ float bsm[3][64];
    __shared__ float keepf[128];
    __shared__ float comb[128];
    __shared__ int f[2];
    const int t = threadIdx.x, wid = t >> 5, lane = t & 31;
    const int g8 = lane >> 3, l8 = lane & 7, l4 = lane >> 2, lq = lane & 3;
    const int bid = blockIdx.x;

    if (t < 2) f[t] = 0;
    if (t < 64) { bsm[0][t] = bq[t]; bsm[1][t] = bk[t]; bsm[2][t] = bv[t]; }

    // ---- L2 prefetch of this CTA's PK/PV slices (hides DRAM latency of the
    //      epilogue modulation loads behind staging + MMAs) ----
    {
        const char* pk = (const char*)(PK + (size_t)bid * 128 * 64);
        const char* pv = (const char*)(PV + (size_t)bid * 128 * 64);
        pref_l2(pk + t * 128);
        pref_l2(pv + t * 128);
    }

    // ---- stage E hi/lo (row = t>>1, half-row of 32 floats per thread) ----
    {
        const int row = t >> 1, half = t & 1;
        const float4* er = reinterpret_cast<const float4*>(
            E + ((size_t)bid * 128 + row) * 64 + half * 32);
        #pragma unroll
        for (int k = 0; k < 4; k++) {
            float4 va = er[2 * k], vb = er[2 * k + 1];
            float v[8] = {va.x, va.y, va.z, va.w, vb.x, vb.y, vb.z, vb.w};
            uint32_t uh[4], ul[4];
            #pragma unroll
            for (int j = 0; j < 4; j++) {
                const __half h0 = __float2half_rn(v[2*j]);
                const __half h1 = __float2half_rn(v[2*j+1]);
                const __half e0 = __float2half_rn(v[2*j]   - __half2float(h0));
                const __half e1 = __float2half_rn(v[2*j+1] - __half2float(h1));
                uh[j] = (uint32_t)__half_as_ushort(h0) | ((uint32_t)__half_as_ushort(h1) << 16);
                ul[j] = (uint32_t)__half_as_ushort(e0) | ((uint32_t)__half_as_ushort(e1) << 16);
            }
            const int c = half * 4 + k;
            const uint32_t sw = (uint32_t)row * 128 + (((uint32_t)(c ^ (row & 7))) << 4);
            sts128(smb + PSE_HI + sw, uh[0], uh[1], uh[2], uh[3]);
            sts128(smb + PSE_LO + sw, ul[0], ul[1], ul[2], ul[3]);
        }
    }

    // ---- stage W hi/lo (3 matrices x 64 rows x 2 half-rows = 384 units) ----
    {
        const float* Wsrc[3] = {Wq, Wk, Wv};
        #pragma unroll
        for (int u = t; u < 384; u += 256) {
            const int m = u >> 7, rem = u & 127, row = rem >> 1, half = rem & 1;
            const float4* wr4 = reinterpret_cast<const float4*>(Wsrc[m] + row * 64 + half * 32);
            #pragma unroll
            for (int k = 0; k < 4; k++) {
                float4 va = wr4[2 * k], vb = wr4[2 * k + 1];
                float v[8] = {va.x, va.y, va.z, va.w, vb.x, vb.y, vb.z, vb.w};
                uint32_t uh[4], ul[4];
                #pragma unroll
                for (int j = 0; j < 4; j++) {
                    const __half h0 = __float2half_rn(v[2*j]);
                    const __half h1 = __float2half_rn(v[2*j+1]);
                    const __half e0 = __float2half_rn(v[2*j]   - __half2float(h0));
                    const __half e1 = __float2half_rn(v[2*j+1] - __half2float(h1));
                    uh[j] = (uint32_t)__half_as_ushort(h0) | ((uint32_t)__half_as_ushort(h1) << 16);
                    ul[j] = (uint32_t)__half_as_ushort(e0) | ((uint32_t)__half_as_ushort(e1) << 16);
                }
                const int c = half * 4 + k;
                const uint32_t sw = (uint32_t)row * 128 + (((uint32_t)(c ^ (row & 7))) << 4);
                const uint32_t base = smb + PSW + m * 16384;
                sts128(base + sw, uh[0], uh[1], uh[2], uh[3]);
                sts128(base + 8192 + sw, ul[0], ul[1], ul[2], ul[3]);
            }
        }
    }

    // ---- pad dtype detection (16KB scan = minimum buffer size) ----
    {
        const uint4* p4 = reinterpret_cast<const uint4*>(pad);
        uint32_t ge2 = 0, odd = 0;
        #pragma unroll
        for (int i = t; i < 1024; i += 256) {
            uint4 v = p4[i];
            uint32_t o = v.x | v.y | v.z | v.w;
            ge2 |= o & 0xFEFEFEFEu;
            odd |= o & 0xFFFFFF00u;
        }
        if (ge2) atomicOr(&f[0], 1);
        if (odd) atomicOr(&f[1], 1);
    }
    __syncthreads();

    // ---- canonical half mask + keep flags for this CTA's 128 rows ----
    if (t < 128) {
        const int kind = f[0] ? 2 : (f[1] ? 0 : 1);   // 0=u8, 1=i32, 2=f32
        const int i = bid * 128 + t;
        bool m;
        if (kind == 0)      m = ((const unsigned char*)pad)[i] != 0;
        else if (kind == 1) m = ((const int*)pad)[i] != 0;
        else                m = ((const float*)pad)[i] != 0.f;
        const float k = m ? 0.f : 1.f;
        keepf[t] = k;
        g_pad1h[i] = __float2half(k);
    }
    __syncthreads();

    // ---- A fragments (E rows, hi/lo), 4 k-chunks of 16 ----
    uint32_t ah[4][4], al[4][4];
    {
        const int arow = wid * 16 + (g8 & 1) * 8 + l8;
        #pragma unroll
        for (int dc = 0; dc < 4; dc++) {
            const int c = 2 * dc + (g8 >> 1);
            const uint32_t a0 = smb + PSE_HI + arow * 128 + (((uint32_t)(c ^ (arow & 7))) << 4);
            ldm_x4(ah[dc], a0);
            ldm_x4(al[dc], a0 + (PSE_LO - PSE_HI));
        }
    }
    __syncthreads();   // all A-frag reads done before red overlays the E area

    const int r0l = wid * 16 + l4;                 // local rows r0l, r0l+8
    const size_t grow0 = (size_t)bid * 128 + r0l;
    const float keep0 = keepf[r0l], keep1 = keepf[r0l + 8];
    float* red = reinterpret_cast<float*>(psm + PSE_HI);   // 128 x 64 fp32 overlay

    __half* gdsts[3] = {g_Qh, g_Kh, g_Vh};

    #pragma unroll 1
    for (int m = 0; m < 3; m++) {
        float C[8][4];
        #pragma unroll
        for (int i = 0; i < 8; i++)
            { C[i][0] = 0.f; C[i][1] = 0.f; C[i][2] = 0.f; C[i][3] = 0.f; }
        const uint32_t wb = smb + PSW + m * 16384;

        #pragma unroll
        for (int nb = 0; nb < 4; nb++) {
            #pragma unroll
            for (int ks = 0; ks < 4; ks++) {
                const int row = nb * 16 + (g8 >> 1) * 8 + l8;
                const int c = 2 * ks + (g8 & 1);
                const uint32_t a = wb + row * 128 + (((uint32_t)(c ^ (row & 7))) << 4);
                uint32_t bh[4], bl[4];
                ldm_x4(bh, a);
                ldm_x4(bl, a + 8192);
                mma_f16(C[2*nb],   ah[ks], bh);
                mma_f16(C[2*nb],   al[ks], bh);
                mma_f16(C[2*nb],   ah[ks], bl);
                mma_f16(C[2*nb+1], ah[ks], bh + 2);
                mma_f16(C[2*nb+1], al[ks], bh + 2);
                mma_f16(C[2*nb+1], ah[ks], bl + 2);
            }
        }

        // ---- epilogue: bias + scale/modulate + keep-zero + fp16 store ----
        __half* gd = gdsts[m];
        #pragma unroll
        for (int i = 0; i < 8; i++) {
            const int c0 = i * 8 + 2 * lq;
            const float b0 = bsm[m][c0], b1 = bsm[m][c0 + 1];
            float v00 = C[i][0] + b0, v01 = C[i][1] + b1;
            float v10 = C[i][2] + b0, v11 = C[i][3] + b1;
            if (m == 0) {
                v00 *= QSCALE; v01 *= QSCALE; v10 *= QSCALE; v11 *= QSCALE;
            } else {
                const float* mod = (m == 1 ? PK : PV);
                const float2 m0 = *reinterpret_cast<const float2*>(mod + grow0 * 64 + c0);
                const float2 m1 = *reinterpret_cast<const float2*>(mod + (grow0 + 8) * 64 + c0);
                v00 *= m0.x; v01 *= m0.y; v10 *= m1.x; v11 *= m1.y;
                if (m == 2) {   // stash UN-zeroed fp32 V_p for meanV
                    *reinterpret_cast<float2*>(&red[r0l * 64 + c0])       = make_float2(v00, v01);
                    *reinterpret_cast<float2*>(&red[(r0l + 8) * 64 + c0]) = make_float2(v10, v11);
                }
                v00 *= keep0; v01 *= keep0; v10 *= keep1; v11 *= keep1;
            }
            *reinterpret_cast<uint32_t*>(&gd[grow0 * 64 + c0])       = cvt_f16x2(v01, v00);
            *reinterpret_cast<uint32_t*>(&gd[(grow0 + 8) * 64 + c0]) = cvt_f16x2(v11, v10);
        }
    }

    // ---- meanV partial for this CTA's 128 rows ----
    __syncthreads();
    if (t < 128) {
        const int col = t & 63, half = t >> 6;
        float a = 0.f;
        #pragma unroll 8
        for (int r = half * 64; r < half * 64 + 64; r++) a += red[r * 64 + col];
        comb[t] = a;
    }
    __syncthreads();
    if (t < 64) g_part[bid][t] = comb[t] + comb[t + 64];
}

// ---------------------------------------------------------------------------
// Kernel 2: single-fp16 mma.sync flash attention, cp.async double-buffered.
// CTA = 256 threads = 2 row-groups (32 q-rows) x 4 key-quarters (32 keys).
// Two-phase pair scheduling (qt, 63-qt): exactly 33 k-tiles per CTA.
// The k-tile loop is unrolled by 2 with COMPILE-TIME stage constants so
// ptxas hoists all swizzled smem address chains out of the loop.
// Padding folded into the GEMMs (zeroed K/V + ones-mask MMA for l).
// ---------------------------------------------------------------------------
constexpr int SM_QH   = 0;                      // 64 x 128B
constexpr int SM_KV   = 8192;                   // 2 stages x (K 16KB + V 16KB)
constexpr int STG_SZ  = 32768;
constexpr int OFF_K   = 0, OFF_V = 16384;
constexpr int SM_PADB = SM_KV + 2 * STG_SZ;     // 73728, 2 x 256B (half mask)
constexpr int SM_LSM  = SM_PADB + 512;          // 74240, 4 x 64 f32
constexpr int SM_MNV  = SM_LSM + 1024;          // 75264, 64 f32
constexpr int SM_MRG  = SM_KV;                  // merge overlays stages (drained)
constexpr int SM_TOTAL = SM_MNV + 256;          // 75520

// One k-tile body with compile-time stage STc (0/1).
#define TILE_BODY(STc, J)                                                      \
do {                                                                           \
    const int kt_ = (J) * NT;                                                  \
    const uint32_t stb_  = smb + (uint32_t)(SM_KV + (STc) * STG_SZ);           \
    const uint32_t padb_ = smb + (uint32_t)(SM_PADB + (STc) * 256);            \
    if ((J) + 1 < nkt) {                                                       \
        const int ktn_ = ((J) + 1) * NT;                                       \
        const uint32_t nstb_ = smb + (uint32_t)(SM_KV + (1 - (STc)) * STG_SZ); \
        const __half* srcK_ = g_Kh + ((size_t)b * S_ + ktn_) * D_;             \
        const __half* srcV_ = g_Vh + ((size_t)b * S_ + ktn_) * D_;             \
        _Pragma("unroll")                                                      \
        for (int it = 0; it < 4; it++) {                                       \
            const int i = tid + it * 256;                                      \
            const int row = i >> 3, c = i & 7;                                 \
            const uint32_t off = (uint32_t)row * 128 +                         \
                                 (((uint32_t)(c ^ (row & 7))) << 4);           \
            cpa16(nstb_ + off,         reinterpret_cast<const uint4*>(srcK_) + i); \
            cpa16(nstb_ + 16384 + off, reinterpret_cast<const uint4*>(srcV_) + i); \
        }                                                                      \
        if (tid < 16)                                                          \
            cpa16(smb + (uint32_t)(SM_PADB + (1 - (STc)) * 256) + tid * 16,    \
                  (const char*)(g_pad1h + b * S_ + ktn_) + tid * 16);          \
        CP_COMMIT();                                                           \
    }                                                                          \
    const bool interior_ = ((J) < nkt - 1);                                    \
    _Pragma("unroll")                                                          \
    for (int kp = 0; kp < 2; kp++) {                                           \
        float SC[2][2][4];                                                     \
        _Pragma("unroll")                                                      \
        for (int rc = 0; rc < 2; rc++)                                         \
            _Pragma("unroll")                                                  \
            for (int n = 0; n < 2; n++)                                        \
                { SC[rc][n][0]=0.f; SC[rc][n][1]=0.f; SC[rc][n][2]=0.f; SC[rc][n][3]=0.f; } \
        {                                                                      \
            const int krow = kb0 + kp * 16 + (g8 >> 1) * 8 + l8;               \
            _Pragma("unroll")                                                  \
            for (int dc = 0; dc < 4; dc++) {                                   \
                const int c = 2 * dc + (g8 & 1);                               \
                uint32_t bh[4];                                                \
                ldm_x4(bh, stb_ + OFF_K + krow * 128 +                         \
                           (((uint32_t)(c ^ (krow & 7))) << 4));               \
                _Pragma("unroll")                                              \
                for (int rc = 0; rc < 2; rc++) {                               \
                    mma_f16(SC[rc][0], qh[rc][dc], bh);                        \
                    mma_f16(SC[rc][1], qh[rc][dc], bh + 2);                    \
                }                                                              \
            }                                                                  \
        }                                                                      \
        uint32_t Ph[2][4];                                                     \
        if (interior_) {                                                       \
            _Pragma("unroll")                                                  \
            for (int rc = 0; rc < 2; rc++)                                     \
                _Pragma("unroll")                                              \
                for (int n = 0; n < 2; n++) {                                  \
                    const float p00 = ex2(SC[rc][n][0]);                       \
                    const float p01 = ex2(SC[rc][n][1]);                       \
                    const float p10 = ex2(SC[rc][n][2]);                       \
                    const float p11 = ex2(SC[rc][n][3]);                       \
                    Ph[rc][n * 2]     = cvt_f16x2(p01, p00);                   \
                    Ph[rc][n * 2 + 1] = cvt_f16x2(p11, p10);                   \
                }                                                              \
        } else {                                                               \
            _Pragma("unroll")                                                  \
            for (int rc = 0; rc < 2; rc++) {                                   \
                const int qr0 = qbase + rg * 32 + rc * 16 + l4;                \
                const int qr1 = qr0 + 8;                                       \
                _Pragma("unroll")                                              \
                for (int n = 0; n < 2; n++) {                                  \
                    const int key = kt_ + kb0 + kp * 16 + n * 8 + 2 * lq;      \
                    const float p00 = (key     <= qr0) ? ex2(SC[rc][n][0]) : 0.f; \
                    const float p01 = (key + 1 <= qr0) ? ex2(SC[rc][n][1]) : 0.f; \
                    const float p10 = (key     <= qr1) ? ex2(SC[rc][n][2]) : 0.f; \
                    const float p11 = (key + 1 <= qr1) ? ex2(SC[rc][n][3]) : 0.f; \
                    Ph[rc][n * 2]     = cvt_f16x2(p01, p00);                   \
                    Ph[rc][n * 2 + 1] = cvt_f16x2(p11, p10);                   \
                }                                                              \
            }                                                                  \
        }                                                                      \
        {                                                                      \
            const uint32_t a = padb_ + (uint32_t)(kb0 + kp * 16 + 2 * lq) * 2; \
            uint32_t bm[2];                                                    \
            bm[0] = lds32(a);                                                  \
            bm[1] = lds32(a + 16);                                             \
            _Pragma("unroll")                                                  \
            for (int rc = 0; rc < 2; rc++) mma_f16(LM[rc], Ph[rc], bm);        \
        }                                                                      \
        {                                                                      \
            const int vrow = kb0 + kp * 16 + (g8 & 1) * 8 + l8;                \
            _Pragma("unroll")                                                  \
            for (int ndp = 0; ndp < 4; ndp++) {                                \
                const int c = 2 * ndp + (g8 >> 1);                             \
                uint32_t bh[4];                                                \
                ldm_x4_t(bh, stb_ + OFF_V + vrow * 128 +                       \
                             (((uint32_t)(c ^ (vrow & 7))) << 4));             \
                _Pragma("unroll")                                              \
                for (int rc = 0; rc < 2; rc++) {                               \
                    mma_f16(OC[rc][2*ndp],   Ph[rc], bh);                      \
                    mma_f16(OC[rc][2*ndp+1], Ph[rc], bh + 2);                  \
                }                                                              \
            }                                                                  \
        }                                                                      \
    }                                                                          \
    if ((J) + 1 < nkt) CP_WAIT0();                                             \
    __syncthreads();                                                           \
} while (0)

__global__ __launch_bounds__(256, 1) void attn_mma_kernel(float* __restrict__ out)
{
    extern __shared__ char sm[];
    const uint32_t smb = smem_u32(sm);
    const int tid = threadIdx.x, wid = tid >> 5, lane = tid & 31;
    const int rg = wid & 1, wc = wid >> 1;        // row-group (0..1), key-quarter (0..3)
    const int b = blockIdx.y;
    const int g8 = lane >> 3, l8 = lane & 7, l4 = lane >> 2, lq = lane & 3;
    float* lsm  = reinterpret_cast<float*>(sm + SM_LSM);
    float* mnv  = reinterpret_cast<float*>(sm + SM_MNV);
    float* mrg  = reinterpret_cast<float*>(sm + SM_MRG);

    // ---- meanV for this batch (sum of 32 proj-CTA partials) ----
    if (tid < 64) {
        float a = 0.f;
        #pragma unroll 8
        for (int i = 0; i < 32; i++) a += g_part[b * 32 + i][tid];
        mnv[tid] = a * (1.0f / (float)S_);
    }

    #pragma unroll 1
    for (int phase = 0; phase < 2; phase++) {
        const int qt = phase ? (63 - blockIdx.x) : blockIdx.x;
        const int qbase = qt * MT;
        const int nkt = (qt >> 1) + 1;

        __syncthreads();   // prev phase merge reads done (and mnv visible)

        // ---- prologue: async-copy Q + k-tile 0 into stage 0 ----
        {
            const uint4* qh4 = reinterpret_cast<const uint4*>(g_Qh + ((size_t)b * S_ + qbase) * D_);
            #pragma unroll
            for (int it = 0; it < 2; it++) {
                int i = tid + it * 256;
                int row = i >> 3, c = i & 7;
                uint32_t sw = row * 128 + (((uint32_t)(c ^ (row & 7))) << 4);
                cpa16(smb + SM_QH + sw, qh4 + i);
            }
            const __half* srcK = g_Kh + (size_t)b * S_ * D_;
            const __half* srcV = g_Vh + (size_t)b * S_ * D_;
            #pragma unroll
            for (int it = 0; it < 4; it++) {
                int i = tid + it * 256;
                int row = i >> 3, c = i & 7;
                uint32_t off = (uint32_t)row * 128 + (((uint32_t)(c ^ (row & 7))) << 4);
                cpa16(smb + SM_KV + off,         reinterpret_cast<const uint4*>(srcK) + i);
                cpa16(smb + SM_KV + 16384 + off, reinterpret_cast<const uint4*>(srcV) + i);
            }
            if (tid < 16)
                cpa16(smb + SM_PADB + tid * 16, (const char*)(g_pad1h + b * S_) + tid * 16);
            CP_COMMIT();
        }
        CP_WAIT0();
        __syncthreads();

        // ---- Q A-fragments: 2 row-chunks x 4 d-chunks ----
        uint32_t qh[2][4][4];
        #pragma unroll
        for (int rc = 0; rc < 2; rc++) {
            const int row = rg * 32 + rc * 16 + (g8 & 1) * 8 + l8;
            #pragma unroll
            for (int dc = 0; dc < 4; dc++) {
                const int c = 2 * dc + (g8 >> 1);
                ldm_x4(qh[rc][dc], smb + SM_QH + row * 128 + (((uint32_t)(c ^ (row & 7))) << 4));
            }
        }

        float OC[2][8][4];
        #pragma unroll
        for (int rc = 0; rc < 2; rc++)
            #pragma unroll
            for (int i = 0; i < 8; i++)
                { OC[rc][i][0] = 0.f; OC[rc][i][1] = 0.f; OC[rc][i][2] = 0.f; OC[rc][i][3] = 0.f; }
        float LM[2][4] = {{0.f,0.f,0.f,0.f},{0.f,0.f,0.f,0.f}};
        const int kb0 = wc * 32;

        // ---- k-tile loop, unrolled by 2 with compile-time stages ----
        #pragma unroll 1
        for (int jj = 0; jj < nkt; jj += 2) {
            TILE_BODY(0, jj);
            if (jj + 1 < nkt) TILE_BODY(1, jj + 1);
        }

        // ---- merge the four key-quarters (ADD; no rescaling needed) ----
        if (lq == 0) {
            #pragma unroll
            for (int rc = 0; rc < 2; rc++) {
                lsm[wc * 64 + rg * 32 + rc * 16 + l4]     = LM[rc][0];
                lsm[wc * 64 + rg * 32 + rc * 16 + 8 + l4] = LM[rc][2];
            }
        }
        if (wc != 0) {
            float* mq = mrg + (wc - 1) * 4096;
            #pragma unroll
            for (int rc = 0; rc < 2; rc++) {
                const int r0 = rg * 32 + rc * 16 + l4;
                #pragma unroll
                for (int nd = 0; nd < 8; nd++) {
                    const int d0 = nd * 8 + 2 * lq;
                    *reinterpret_cast<float2*>(&mq[r0 * 64 + d0]) =
                        make_float2(OC[rc][nd][0], OC[rc][nd][1]);
                    *reinterpret_cast<float2*>(&mq[(r0 + 8) * 64 + d0]) =
                        make_float2(OC[rc][nd][2], OC[rc][nd][3]);
                }
            }
        }
        __syncthreads();
        if (wc == 0) {
            #pragma unroll
            for (int rc = 0; rc < 2; rc++) {
                const int r0 = rg * 32 + rc * 16 + l4;
                const float lt0 = lsm[r0] + lsm[64 + r0] + lsm[128 + r0] + lsm[192 + r0];
                const float lt1 = lsm[r0 + 8] + lsm[64 + r0 + 8] + lsm[128 + r0 + 8] + lsm[192 + r0 + 8];
                const bool am0 = (lt0 == 0.f), am1 = (lt1 == 0.f);
                const float inv0 = am0 ? 0.f : 1.f / lt0;
                const float inv1 = am1 ? 0.f : 1.f / lt1;
                const int qr0 = qbase + r0, qr1 = qr0 + 8;
                #pragma unroll
                for (int nd = 0; nd < 8; nd++) {
                    const int d0 = nd * 8 + 2 * lq;
                    float a0 = OC[rc][nd][0], a1 = OC[rc][nd][1];
                    float a2 = OC[rc][nd][2], a3 = OC[rc][nd][3];
                    #pragma unroll
                    for (int qq = 0; qq < 3; qq++) {
                        const float* mq = mrg + qq * 4096;
                        const float2 m0v = *reinterpret_cast<const float2*>(&mq[r0 * 64 + d0]);
                        const float2 m1v = *reinterpret_cast<const float2*>(&mq[(r0 + 8) * 64 + d0]);
                        a0 += m0v.x; a1 += m0v.y; a2 += m1v.x; a3 += m1v.y;
                    }
                    float2 o0, o1;
                    if (am0) o0 = make_float2(mnv[d0], mnv[d0 + 1]);
                    else     o0 = make_float2(a0 * inv0, a1 * inv0);
                    if (am1) o1 = make_float2(mnv[d0], mnv[d0 + 1]);
                    else     o1 = make_float2(a2 * inv1, a3 * inv1);
                    *reinterpret_cast<float2*>(&out[((size_t)b * S_ + qr0) * D_ + d0]) = o0;
                    *reinterpret_cast<float2*>(&out[((size_t)b * S_ + qr1) * D_ + d0]) = o1;
                }
            }
        }
    }
}

// ---------------------------------------------------------------------------
extern "C" void kernel_launch(void* const* d_in, const int* in_sizes, int n_in,
                              void* d_out, int out_size)
{
    const float* E  = (const float*)d_in[0];
    const float* PK = (const float*)d_in[1];
    const float* PV = (const float*)d_in[2];
    const float* Wq = (const float*)d_in[3];
    const float* bq = (const float*)d_in[4];
    const float* Wk = (const float*)d_in[5];
    const float* bk = (const float*)d_in[6];
    const float* Wv = (const float*)d_in[7];
    const float* bv = (const float*)d_in[8];
    const void*  pad = d_in[9];
    float* out = (float*)d_out;

    cudaFuncSetAttribute(proj_kernel, cudaFuncAttributeMaxDynamicSharedMemorySize, PROJ_SMEM);
    cudaFuncSetAttribute(attn_mma_kernel, cudaFuncAttributeMaxDynamicSharedMemorySize, SM_TOTAL);

    proj_kernel<<<128, 256, PROJ_SMEM>>>(E, PK, PV, Wq, bq, Wk, bk, Wv, bv, pad);
    attn_mma_kernel<<<dim3(32, B_), 256, SM_TOTAL>>>(out);
}

// round 16
// speedup vs baseline: 1.0835x; 1.0835x over previous
#include <cuda_runtime.h>
#include <cuda_fp16.h>
#include <math.h>
#include <stdint.h>

// Problem constants
constexpr int B_ = 4, S_ = 4096, D_ = 64;
constexpr int MT = 64;            // q rows per tile (one phase)
constexpr int NT = 128;           // keys per k-tile
constexpr float QSCALE = 0.18033688011112042f;  // 0.125 * log2(e), folded into Q

// ---- global scratch (allocation-free rule) ----
__device__ __align__(16) __half g_Qh[B_*S_*D_];
__device__ __align__(16) __half g_Kh[B_*S_*D_];   // zeroed on padded keys
__device__ __align__(16) __half g_Vh[B_*S_*D_];   // zeroed on padded keys
__device__ __align__(16) __half g_pad1h[B_*S_];   // 1.0 keep / 0.0 masked
__device__ float g_part[128][D_];                 // V_p column sums per proj CTA

__device__ __forceinline__ uint32_t smem_u32(const void* p) {
    uint32_t a;
    asm("{ .reg .u64 t; cvta.to.shared.u64 t, %1; cvt.u32.u64 %0, t; }" : "=r"(a) : "l"(p));
    return a;
}

// ---- mma.sync / ldmatrix / misc PTX ----
__device__ __forceinline__ void ldm_x4(uint32_t* r, uint32_t a) {
    asm volatile("ldmatrix.sync.aligned.m8n8.x4.shared.b16 {%0,%1,%2,%3}, [%4];"
                 : "=r"(r[0]), "=r"(r[1]), "=r"(r[2]), "=r"(r[3]) : "r"(a));
}
__device__ __forceinline__ void ldm_x4_t(uint32_t* r, uint32_t a) {
    asm volatile("ldmatrix.sync.aligned.m8n8.x4.trans.shared.b16 {%0,%1,%2,%3}, [%4];"
                 : "=r"(r[0]), "=r"(r[1]), "=r"(r[2]), "=r"(r[3]) : "r"(a));
}
__device__ __forceinline__ void mma_f16(float* c, const uint32_t* a, const uint32_t* b) {
    asm volatile("mma.sync.aligned.m16n8k16.row.col.f32.f16.f16.f32 "
                 "{%0,%1,%2,%3}, {%4,%5,%6,%7}, {%8,%9}, {%0,%1,%2,%3};"
                 : "+f"(c[0]), "+f"(c[1]), "+f"(c[2]), "+f"(c[3])
                 : "r"(a[0]), "r"(a[1]), "r"(a[2]), "r"(a[3]), "r"(b[0]), "r"(b[1]));
}
// packed fp16 exp2: input f16x2, output f16x2 (one MUFU op for two values)
__device__ __forceinline__ uint32_t ex2_f16x2(uint32_t x) {
    uint32_t y; asm("ex2.approx.f16x2 %0, %1;" : "=r"(y) : "r"(x)); return y;
}
// pack two fp32 -> fp16x2; second arg lands in the LOW half
__device__ __forceinline__ uint32_t cvt_f16x2(float hi, float lo) {
    uint32_t r; asm("cvt.rn.f16x2.f32 %0, %1, %2;" : "=r"(r) : "f"(hi), "f"(lo)); return r;
}
__device__ __forceinline__ uint32_t lds32(uint32_t a) {
    uint32_t v; asm volatile("ld.shared.b32 %0, [%1];" : "=r"(v) : "r"(a)); return v;
}
__device__ __forceinline__ void sts128(uint32_t a, uint32_t x, uint32_t y, uint32_t z, uint32_t w) {
    asm volatile("st.shared.v4.b32 [%0], {%1,%2,%3,%4};"
                 :: "r"(a), "r"(x), "r"(y), "r"(z), "r"(w) : "memory");
}
__device__ __forceinline__ void cpa16(uint32_t dst, const void* src) {
    asm volatile("cp.async.cg.shared.global [%0], [%1], 16;" :: "r"(dst), "l"(src));
}
#define CP_COMMIT() asm volatile("cp.async.commit_group;" ::: "memory")
#define CP_WAIT0()  asm volatile("cp.async.wait_group 0;" ::: "memory")

// ---------------------------------------------------------------------------
// Kernel 1: tensor-core QKV projection (round-13 measured-best; no prefetch).
// D = E @ W^T emulated in fp32 precision by fp16 hi/lo (3 combos).
// Also: pad dtype detect + canonical half mask, padded-K/V zeroing, and
// per-CTA fp32 V_p column sums (meanV). 128 CTAs x 256 threads.
// ---------------------------------------------------------------------------
constexpr int PSE_HI = 0;                       // E hi: 128 x 128B (swizzled)
constexpr int PSE_LO = 16384;                   // E lo
constexpr int PSW    = 32768;                   // W: 3 x (hi 8KB + lo 8KB)
constexpr int PROJ_SMEM = PSW + 3 * 16384;      // 81920

__global__ __launch_bounds__(256) void proj_kernel(
    const float* __restrict__ E,  const float* __restrict__ PK, const float* __restrict__ PV,
    const float* __restrict__ Wq, const float* __restrict__ bq,
    const float* __restrict__ Wk, const float* __restrict__ bk,
    const float* __restrict__ Wv, const float* __restrict__ bv,
    const void* __restrict__ pad)
{
    extern __shared__ char psm[];
    const uint32_t smb = smem_u32(psm);
    __shared__ float bsm[3][64];
    __shared__ float keepf[128];
    __shared__ float comb[128];
    __shared__ int f[2];
    const int t = threadIdx.x, wid = t >> 5, lane = t & 31;
    const int g8 = lane >> 3, l8 = lane & 7, l4 = lane >> 2, lq = lane & 3;
    const int bid = blockIdx.x;

    if (t < 2) f[t] = 0;
    if (t < 64) { bsm[0][t] = bq[t]; bsm[1][t] = bk[t]; bsm[2][t] = bv[t]; }

    // ---- stage E hi/lo (row = t>>1, half-row of 32 floats per thread) ----
    {
        const int row = t >> 1, half = t & 1;
        const float4* er = reinterpret_cast<const float4*>(
            E + ((size_t)bid * 128 + row) * 64 + half * 32);
        #pragma unroll
        for (int k = 0; k < 4; k++) {
            float4 va = er[2 * k], vb = er[2 * k + 1];
            float v[8] = {va.x, va.y, va.z, va.w, vb.x, vb.y, vb.z, vb.w};
            uint32_t uh[4], ul[4];
            #pragma unroll
            for (int j = 0; j < 4; j++) {
                const __half h0 = __float2half_rn(v[2*j]);
                const __half h1 = __float2half_rn(v[2*j+1]);
                const __half e0 = __float2half_rn(v[2*j]   - __half2float(h0));
                const __half e1 = __float2half_rn(v[2*j+1] - __half2float(h1));
                uh[j] = (uint32_t)__half_as_ushort(h0) | ((uint32_t)__half_as_ushort(h1) << 16);
                ul[j] = (uint32_t)__half_as_ushort(e0) | ((uint32_t)__half_as_ushort(e1) << 16);
            }
            const int c = half * 4 + k;
            const uint32_t sw = (uint32_t)row * 128 + (((uint32_t)(c ^ (row & 7))) << 4);
            sts128(smb + PSE_HI + sw, uh[0], uh[1], uh[2], uh[3]);
            sts128(smb + PSE_LO + sw, ul[0], ul[1], ul[2], ul[3]);
        }
    }

    // ---- stage W hi/lo (3 matrices x 64 rows x 2 half-rows = 384 units) ----
    {
        const float* Wsrc[3] = {Wq, Wk, Wv};
        #pragma unroll
        for (int u = t; u < 384; u += 256) {
            const int m = u >> 7, rem = u & 127, row = rem >> 1, half = rem & 1;
            const float4* wr4 = reinterpret_cast<const float4*>(Wsrc[m] + row * 64 + half * 32);
            #pragma unroll
            for (int k = 0; k < 4; k++) {
                float4 va = wr4[2 * k], vb = wr4[2 * k + 1];
                float v[8] = {va.x, va.y, va.z, va.w, vb.x, vb.y, vb.z, vb.w};
                uint32_t uh[4], ul[4];
                #pragma unroll
                for (int j = 0; j < 4; j++) {
                    const __half h0 = __float2half_rn(v[2*j]);
                    const __half h1 = __float2half_rn(v[2*j+1]);
                    const __half e0 = __float2half_rn(v[2*j]   - __half2float(h0));
                    const __half e1 = __float2half_rn(v[2*j+1] - __half2float(h1));
                    uh[j] = (uint32_t)__half_as_ushort(h0) | ((uint32_t)__half_as_ushort(h1) << 16);
                    ul[j] = (uint32_t)__half_as_ushort(e0) | ((uint32_t)__half_as_ushort(e1) << 16);
                }
                const int c = half * 4 + k;
                const uint32_t sw = (uint32_t)row * 128 + (((uint32_t)(c ^ (row & 7))) << 4);
                const uint32_t base = smb + PSW + m * 16384;
                sts128(base + sw, uh[0], uh[1], uh[2], uh[3]);
                sts128(base + 8192 + sw, ul[0], ul[1], ul[2], ul[3]);
            }
        }
    }

    // ---- pad dtype detection (16KB scan = minimum buffer size) ----
    {
        const uint4* p4 = reinterpret_cast<const uint4*>(pad);
        uint32_t ge2 = 0, odd = 0;
        #pragma unroll
        for (int i = t; i < 1024; i += 256) {
            uint4 v = p4[i];
            uint32_t o = v.x | v.y | v.z | v.w;
            ge2 |= o & 0xFEFEFEFEu;
            odd |= o & 0xFFFFFF00u;
        }
        if (ge2) atomicOr(&f[0], 1);
        if (odd) atomicOr(&f[1], 1);
    }
    __syncthreads();

    // ---- canonical half mask + keep flags for this CTA's 128 rows ----
    if (t < 128) {
        const int kind = f[0] ? 2 : (f[1] ? 0 : 1);   // 0=u8, 1=i32, 2=f32
        const int i = bid * 128 + t;
        bool m;
        if (kind == 0)      m = ((const unsigned char*)pad)[i] != 0;
        else if (kind == 1) m = ((const int*)pad)[i] != 0;
        else                m = ((const float*)pad)[i] != 0.f;
        const float k = m ? 0.f : 1.f;
        keepf[t] = k;
        g_pad1h[i] = __float2half(k);
    }
    __syncthreads();

    // ---- A fragments (E rows, hi/lo), 4 k-chunks of 16 ----
    uint32_t ah[4][4], al[4][4];
    {
        const int arow = wid * 16 + (g8 & 1) * 8 + l8;
        #pragma unroll
        for (int dc = 0; dc < 4; dc++) {
            const int c = 2 * dc + (g8 >> 1);
            const uint32_t a0 = smb + PSE_HI + arow * 128 + (((uint32_t)(c ^ (arow & 7))) << 4);
            ldm_x4(ah[dc], a0);
            ldm_x4(al[dc], a0 + (PSE_LO - PSE_HI));
        }
    }
    __syncthreads();   // all A-frag reads done before red overlays the E area

    const int r0l = wid * 16 + l4;                 // local rows r0l, r0l+8
    const size_t grow0 = (size_t)bid * 128 + r0l;
    const float keep0 = keepf[r0l], keep1 = keepf[r0l + 8];
    float* red = reinterpret_cast<float*>(psm + PSE_HI);   // 128 x 64 fp32 overlay

    __half* gdsts[3] = {g_Qh, g_Kh, g_Vh};

    #pragma unroll 1
    for (int m = 0; m < 3; m++) {
        float C[8][4];
        #pragma unroll
        for (int i = 0; i < 8; i++)
            { C[i][0] = 0.f; C[i][1] = 0.f; C[i][2] = 0.f; C[i][3] = 0.f; }
        const uint32_t wb = smb + PSW + m * 16384;

        #pragma unroll
        for (int nb = 0; nb < 4; nb++) {
            #pragma unroll
            for (int ks = 0; ks < 4; ks++) {
                const int row = nb * 16 + (g8 >> 1) * 8 + l8;
                const int c = 2 * ks + (g8 & 1);
                const uint32_t a = wb + row * 128 + (((uint32_t)(c ^ (row & 7))) << 4);
                uint32_t bh[4], bl[4];
                ldm_x4(bh, a);
                ldm_x4(bl, a + 8192);
                mma_f16(C[2*nb],   ah[ks], bh);
                mma_f16(C[2*nb],   al[ks], bh);
                mma_f16(C[2*nb],   ah[ks], bl);
                mma_f16(C[2*nb+1], ah[ks], bh + 2);
                mma_f16(C[2*nb+1], al[ks], bh + 2);
                mma_f16(C[2*nb+1], ah[ks], bl + 2);
            }
        }

        // ---- epilogue: bias + scale/modulate + keep-zero + fp16 store ----
        __half* gd = gdsts[m];
        #pragma unroll
        for (int i = 0; i < 8; i++) {
            const int c0 = i * 8 + 2 * lq;
            const float b0 = bsm[m][c0], b1 = bsm[m][c0 + 1];
            float v00 = C[i][0] + b0, v01 = C[i][1] + b1;
            float v10 = C[i][2] + b0, v11 = C[i][3] + b1;
            if (m == 0) {
                v00 *= QSCALE; v01 *= QSCALE; v10 *= QSCALE; v11 *= QSCALE;
            } else {
                const float* mod = (m == 1 ? PK : PV);
                const float2 m0 = *reinterpret_cast<const float2*>(mod + grow0 * 64 + c0);
                const float2 m1 = *reinterpret_cast<const float2*>(mod + (grow0 + 8) * 64 + c0);
                v00 *= m0.x; v01 *= m0.y; v10 *= m1.x; v11 *= m1.y;
                if (m == 2) {   // stash UN-zeroed fp32 V_p for meanV
                    *reinterpret_cast<float2*>(&red[r0l * 64 + c0])       = make_float2(v00, v01);
                    *reinterpret_cast<float2*>(&red[(r0l + 8) * 64 + c0]) = make_float2(v10, v11);
                }
                v00 *= keep0; v01 *= keep0; v10 *= keep1; v11 *= keep1;
            }
            *reinterpret_cast<uint32_t*>(&gd[grow0 * 64 + c0])       = cvt_f16x2(v01, v00);
            *reinterpret_cast<uint32_t*>(&gd[(grow0 + 8) * 64 + c0]) = cvt_f16x2(v11, v10);
        }
    }

    // ---- meanV partial for this CTA's 128 rows ----
    __syncthreads();
    if (t < 128) {
        const int col = t & 63, half = t >> 6;
        float a = 0.f;
        #pragma unroll 8
        for (int r = half * 64; r < half * 64 + 64; r++) a += red[r * 64 + col];
        comb[t] = a;
    }
    __syncthreads();
    if (t < 64) g_part[bid][t] = comb[t] + comb[t + 64];
}

// ---------------------------------------------------------------------------
// Kernel 2: single-fp16 mma.sync flash attention, cp.async double-buffered.
// CTA = 256 threads = 2 row-groups (32 q-rows) x 4 key-quarters (32 keys).
// Two-phase pair scheduling (qt, 63-qt): exactly 33 k-tiles per CTA.
// k-tile loop unrolled by 2 with compile-time stage constants.
// NEW: softmax exp via packed ex2.approx.f16x2 (cvt s->f16x2 then one MUFU
// op yields the P fragment directly); causal zeroing via bitwise AND.
// Padding folded into the GEMMs (zeroed K/V + ones-mask MMA for l).
// ---------------------------------------------------------------------------
constexpr int SM_QH   = 0;                      // 64 x 128B
constexpr int SM_KV   = 8192;                   // 2 stages x (K 16KB + V 16KB)
constexpr int STG_SZ  = 32768;
constexpr int OFF_K   = 0, OFF_V = 16384;
constexpr int SM_PADB = SM_KV + 2 * STG_SZ;     // 73728, 2 x 256B (half mask)
constexpr int SM_LSM  = SM_PADB + 512;          // 74240, 4 x 64 f32
constexpr int SM_MNV  = SM_LSM + 1024;          // 75264, 64 f32
constexpr int SM_MRG  = SM_KV;                  // merge overlays stages (drained)
constexpr int SM_TOTAL = SM_MNV + 256;          // 75520

// One k-tile body with compile-time stage STc (0/1).
#define TILE_BODY(STc, J)                                                      \
do {                                                                           \
    const int kt_ = (J) * NT;                                                  \
    const uint32_t stb_  = smb + (uint32_t)(SM_KV + (STc) * STG_SZ);           \
    const uint32_t padb_ = smb + (uint32_t)(SM_PADB + (STc) * 256);            \
    if ((J) + 1 < nkt) {                                                       \
        const int ktn_ = ((J) + 1) * NT;                                       \
        const uint32_t nstb_ = smb + (uint32_t)(SM_KV + (1 - (STc)) * STG_SZ); \
        const __half* srcK_ = g_Kh + ((size_t)b * S_ + ktn_) * D_;             \
        const __half* srcV_ = g_Vh + ((size_t)b * S_ + ktn_) * D_;             \
        _Pragma("unroll")                                                      \
        for (int it = 0; it < 4; it++) {                                       \
            const int i = tid + it * 256;                                      \
            const int row = i >> 3, c = i & 7;                                 \
            const uint32_t off = (uint32_t)row * 128 +                         \
                                 (((uint32_t)(c ^ (row & 7))) << 4);           \
            cpa16(nstb_ + off,         reinterpret_cast<const uint4*>(srcK_) + i); \
            cpa16(nstb_ + 16384 + off, reinterpret_cast<const uint4*>(srcV_) + i); \
        }                                                                      \
        if (tid < 16)                                                          \
            cpa16(smb + (uint32_t)(SM_PADB + (1 - (STc)) * 256) + tid * 16,    \
                  (const char*)(g_pad1h + b * S_ + ktn_) + tid * 16);          \
        CP_COMMIT();                                                           \
    }                                                                          \
    const bool interior_ = ((J) < nkt - 1);                                    \
    _Pragma("unroll")                                                          \
    for (int kp = 0; kp < 2; kp++) {                                           \
        float SC[2][2][4];                                                     \
        _Pragma("unroll")                                                      \
        for (int rc = 0; rc < 2; rc++)                                         \
            _Pragma("unroll")                                                  \
            for (int n = 0; n < 2; n++)                                        \
                { SC[rc][n][0]=0.f; SC[rc][n][1]=0.f; SC[rc][n][2]=0.f; SC[rc][n][3]=0.f; } \
        {                                                                      \
            const int krow = kb0 + kp * 16 + (g8 >> 1) * 8 + l8;               \
            _Pragma("unroll")                                                  \
            for (int dc = 0; dc < 4; dc++) {                                   \
                const int c = 2 * dc + (g8 & 1);                               \
                uint32_t bh[4];                                                \
                ldm_x4(bh, stb_ + OFF_K + krow * 128 +                         \
                           (((uint32_t)(c ^ (krow & 7))) << 4));               \
                _Pragma("unroll")                                              \
                for (int rc = 0; rc < 2; rc++) {                               \
                    mma_f16(SC[rc][0], qh[rc][dc], bh);                        \
                    mma_f16(SC[rc][1], qh[rc][dc], bh + 2);                    \
                }                                                              \
            }                                                                  \
        }                                                                      \
        uint32_t Ph[2][4];                                                     \
        if (interior_) {                                                       \
            _Pragma("unroll")                                                  \
            for (int rc = 0; rc < 2; rc++)                                     \
                _Pragma("unroll")                                              \
                for (int n = 0; n < 2; n++) {                                  \
                    Ph[rc][n * 2]     = ex2_f16x2(cvt_f16x2(SC[rc][n][1], SC[rc][n][0])); \
                    Ph[rc][n * 2 + 1] = ex2_f16x2(cvt_f16x2(SC[rc][n][3], SC[rc][n][2])); \
                }                                                              \
        } else {                                                               \
            _Pragma("unroll")                                                  \
            for (int rc = 0; rc < 2; rc++) {                                   \
                const int qr0 = qbase + rg * 32 + rc * 16 + l4;                \
                const int qr1 = qr0 + 8;                                       \
                _Pragma("unroll")                                              \
                for (int n = 0; n < 2; n++) {                                  \
                    const int key = kt_ + kb0 + kp * 16 + n * 8 + 2 * lq;      \
                    const uint32_t mA = (key <= qr0 ? 0xFFFFu : 0u) |          \
                                        (key + 1 <= qr0 ? 0xFFFF0000u : 0u);   \
                    const uint32_t mB = (key <= qr1 ? 0xFFFFu : 0u) |          \
                                        (key + 1 <= qr1 ? 0xFFFF0000u : 0u);   \
                    Ph[rc][n * 2]     = ex2_f16x2(cvt_f16x2(SC[rc][n][1], SC[rc][n][0])) & mA; \
                    Ph[rc][n * 2 + 1] = ex2_f16x2(cvt_f16x2(SC[rc][n][3], SC[rc][n][2])) & mB; \
                }                                                              \
            }                                                                  \
        }                                                                      \
        {                                                                      \
            const uint32_t a = padb_ + (uint32_t)(kb0 + kp * 16 + 2 * lq) * 2; \
            uint32_t bm[2];                                                    \
            bm[0] = lds32(a);                                                  \
            bm[1] = lds32(a + 16);                                             \
            _Pragma("unroll")                                                  \
            for (int rc = 0; rc < 2; rc++) mma_f16(LM[rc], Ph[rc], bm);        \
        }                                                                      \
        {                                                                      \
            const int vrow = kb0 + kp * 16 + (g8 & 1) * 8 + l8;                \
            _Pragma("unroll")                                                  \
            for (int ndp = 0; ndp < 4; ndp++) {                                \
                const int c = 2 * ndp + (g8 >> 1);                             \
                uint32_t bh[4];                                                \
                ldm_x4_t(bh, stb_ + OFF_V + vrow * 128 +                       \
                             (((uint32_t)(c ^ (vrow & 7))) << 4));             \
                _Pragma("unroll")                                              \
                for (int rc = 0; rc < 2; rc++) {                               \
                    mma_f16(OC[rc][2*ndp],   Ph[rc], bh);                      \
                    mma_f16(OC[rc][2*ndp+1], Ph[rc], bh + 2);                  \
                }                                                              \
            }                                                                  \
        }                                                                      \
    }                                                                          \
    if ((J) + 1 < nkt) CP_WAIT0();                                             \
    __syncthreads();                                                           \
} while (0)

__global__ __launch_bounds__(256, 1) void attn_mma_kernel(float* __restrict__ out)
{
    extern __shared__ char sm[];
    const uint32_t smb = smem_u32(sm);
    const int tid = threadIdx.x, wid = tid >> 5, lane = tid & 31;
    const int rg = wid & 1, wc = wid >> 1;        // row-group (0..1), key-quarter (0..3)
    const int b = blockIdx.y;
    const int g8 = lane >> 3, l8 = lane & 7, l4 = lane >> 2, lq = lane & 3;
    float* lsm  = reinterpret_cast<float*>(sm + SM_LSM);
    float* mnv  = reinterpret_cast<float*>(sm + SM_MNV);
    float* mrg  = reinterpret_cast<float*>(sm + SM_MRG);

    // ---- meanV for this batch (sum of 32 proj-CTA partials) ----
    if (tid < 64) {
        float a = 0.f;
        #pragma unroll 8
        for (int i = 0; i < 32; i++) a += g_part[b * 32 + i][tid];
        mnv[tid] = a * (1.0f / (float)S_);
    }

    #pragma unroll 1
    for (int phase = 0; phase < 2; phase++) {
        const int qt = phase ? (63 - blockIdx.x) : blockIdx.x;
        const int qbase = qt * MT;
        const int nkt = (qt >> 1) + 1;

        __syncthreads();   // prev phase merge reads done (and mnv visible)

        // ---- prologue: async-copy Q + k-tile 0 into stage 0 ----
        {
            const uint4* qh4 = reinterpret_cast<const uint4*>(g_Qh + ((size_t)b * S_ + qbase) * D_);
            #pragma unroll
            for (int it = 0; it < 2; it++) {
                int i = tid + it * 256;
                int row = i >> 3, c = i & 7;
                uint32_t sw = row * 128 + (((uint32_t)(c ^ (row & 7))) << 4);
                cpa16(smb + SM_QH + sw, qh4 + i);
            }
            const __half* srcK = g_Kh + (size_t)b * S_ * D_;
            const __half* srcV = g_Vh + (size_t)b * S_ * D_;
            #pragma unroll
            for (int it = 0; it < 4; it++) {
                int i = tid + it * 256;
                int row = i >> 3, c = i & 7;
                uint32_t off = (uint32_t)row * 128 + (((uint32_t)(c ^ (row & 7))) << 4);
                cpa16(smb + SM_KV + off,         reinterpret_cast<const uint4*>(srcK) + i);
                cpa16(smb + SM_KV + 16384 + off, reinterpret_cast<const uint4*>(srcV) + i);
            }
            if (tid < 16)
                cpa16(smb + SM_PADB + tid * 16, (const char*)(g_pad1h + b * S_) + tid * 16);
            CP_COMMIT();
        }
        CP_WAIT0();
        __syncthreads();

        // ---- Q A-fragments: 2 row-chunks x 4 d-chunks ----
        uint32_t qh[2][4][4];
        #pragma unroll
        for (int rc = 0; rc < 2; rc++) {
            const int row = rg * 32 + rc * 16 + (g8 & 1) * 8 + l8;
            #pragma unroll
            for (int dc = 0; dc < 4; dc++) {
                const int c = 2 * dc + (g8 >> 1);
                ldm_x4(qh[rc][dc], smb + SM_QH + row * 128 + (((uint32_t)(c ^ (row & 7))) << 4));
            }
        }

        float OC[2][8][4];
        #pragma unroll
        for (int rc = 0; rc < 2; rc++)
            #pragma unroll
            for (int i = 0; i < 8; i++)
                { OC[rc][i][0] = 0.f; OC[rc][i][1] = 0.f; OC[rc][i][2] = 0.f; OC[rc][i][3] = 0.f; }
        float LM[2][4] = {{0.f,0.f,0.f,0.f},{0.f,0.f,0.f,0.f}};
        const int kb0 = wc * 32;

        // ---- k-tile loop, unrolled by 2 with compile-time stages ----
        #pragma unroll 1
        for (int jj = 0; jj < nkt; jj += 2) {
            TILE_BODY(0, jj);
            if (jj + 1 < nkt) TILE_BODY(1, jj + 1);
        }

        // ---- merge the four key-quarters (ADD; no rescaling needed) ----
        if (lq == 0) {
            #pragma unroll
            for (int rc = 0; rc < 2; rc++) {
                lsm[wc * 64 + rg * 32 + rc * 16 + l4]     = LM[rc][0];
                lsm[wc * 64 + rg * 32 + rc * 16 + 8 + l4] = LM[rc][2];
            }
        }
        if (wc != 0) {
            float* mq = mrg + (wc - 1) * 4096;
            #pragma unroll
            for (int rc = 0; rc < 2; rc++) {
                const int r0 = rg * 32 + rc * 16 + l4;
                #pragma unroll
                for (int nd = 0; nd < 8; nd++) {
                    const int d0 = nd * 8 + 2 * lq;
                    *reinterpret_cast<float2*>(&mq[r0 * 64 + d0]) =
                        make_float2(OC[rc][nd][0], OC[rc][nd][1]);
                    *reinterpret_cast<float2*>(&mq[(r0 + 8) * 64 + d0]) =
                        make_float2(OC[rc][nd][2], OC[rc][nd][3]);
                }
            }
        }
        __syncthreads();
        if (wc == 0) {
            #pragma unroll
            for (int rc = 0; rc < 2; rc++) {
                const int r0 = rg * 32 + rc * 16 + l4;
                const float lt0 = lsm[r0] + lsm[64 + r0] + lsm[128 + r0] + lsm[192 + r0];
                const float lt1 = lsm[r0 + 8] + lsm[64 + r0 + 8] + lsm[128 + r0 + 8] + lsm[192 + r0 + 8];
                const bool am0 = (lt0 == 0.f), am1 = (lt1 == 0.f);
                const float inv0 = am0 ? 0.f : 1.f / lt0;
                const float inv1 = am1 ? 0.f : 1.f / lt1;
                const int qr0 = qbase + r0, qr1 = qr0 + 8;
                #pragma unroll
                for (int nd = 0; nd < 8; nd++) {
                    const int d0 = nd * 8 + 2 * lq;
                    float a0 = OC[rc][nd][0], a1 = OC[rc][nd][1];
                    float a2 = OC[rc][nd][2], a3 = OC[rc][nd][3];
                    #pragma unroll
                    for (int qq = 0; qq < 3; qq++) {
                        const float* mq = mrg + qq * 4096;
                        const float2 m0v = *reinterpret_cast<const float2*>(&mq[r0 * 64 + d0]);
                        const float2 m1v = *reinterpret_cast<const float2*>(&mq[(r0 + 8) * 64 + d0]);
                        a0 += m0v.x; a1 += m0v.y; a2 += m1v.x; a3 += m1v.y;
                    }
                    float2 o0, o1;
                    if (am0) o0 = make_float2(mnv[d0], mnv[d0 + 1]);
                    else     o0 = make_float2(a0 * inv0, a1 * inv0);
                    if (am1) o1 = make_float2(mnv[d0], mnv[d0 + 1]);
                    else     o1 = make_float2(a2 * inv1, a3 * inv1);
                    *reinterpret_cast<float2*>(&out[((size_t)b * S_ + qr0) * D_ + d0]) = o0;
                    *reinterpret_cast<float2*>(&out[((size_t)b * S_ + qr1) * D_ + d0]) = o1;
                }
            }
        }
    }
}

// ---------------------------------------------------------------------------
extern "C" void kernel_launch(void* const* d_in, const int* in_sizes, int n_in,
                              void* d_out, int out_size)
{
    const float* E  = (const float*)d_in[0];
    const float* PK = (const float*)d_in[1];
    const float* PV = (const float*)d_in[2];
    const float* Wq = (const float*)d_in[3];
    const float* bq = (const float*)d_in[4];
    const float* Wk = (const float*)d_in[5];
    const float* bk = (const float*)d_in[6];
    const float* Wv = (const float*)d_in[7];
    const float* bv = (const float*)d_in[8];
    const void*  pad = d_in[9];
    float* out = (float*)d_out;

    cudaFuncSetAttribute(proj_kernel, cudaFuncAttributeMaxDynamicSharedMemorySize, PROJ_SMEM);
    cudaFuncSetAttribute(attn_mma_kernel, cudaFuncAttributeMaxDynamicSharedMemorySize, SM_TOTAL);

    proj_kernel<<<128, 256, PROJ_SMEM>>>(E, PK, PV, Wq, bq, Wk, bk, Wv, bv, pad);
    attn_mma_kernel<<<dim3(32, B_), 256, SM_TOTAL>>>(out);
}

// round 17
// speedup vs baseline: 1.0849x; 1.0012x over previous
#include <cuda_runtime.h>
#include <cuda_fp16.h>
#include <math.h>
#include <stdint.h>

// Problem constants
constexpr int B_ = 4, S_ = 4096, D_ = 64;
constexpr int MT = 64;            // q rows per tile (one phase)
constexpr int NT = 256;           // keys per k-tile
constexpr float QSCALE = 0.18033688011112042f;  // 0.125 * log2(e), folded into Q

// ---- global scratch (allocation-free rule) ----
__device__ __align__(16) __half g_Qh[B_*S_*D_];
__device__ __align__(16) __half g_Kh[B_*S_*D_];   // zeroed on padded keys
__device__ __align__(16) __half g_Vh[B_*S_*D_];   // zeroed on padded keys
__device__ __align__(16) __half g_pad1h[B_*S_];   // 1.0 keep / 0.0 masked
__device__ float g_part[128][D_];                 // V_p column sums per proj CTA

__device__ __forceinline__ uint32_t smem_u32(const void* p) {
    uint32_t a;
    asm("{ .reg .u64 t; cvta.to.shared.u64 t, %1; cvt.u32.u64 %0, t; }" : "=r"(a) : "l"(p));
    return a;
}

// ---- mma.sync / ldmatrix / misc PTX ----
__device__ __forceinline__ void ldm_x4(uint32_t* r, uint32_t a) {
    asm volatile("ldmatrix.sync.aligned.m8n8.x4.shared.b16 {%0,%1,%2,%3}, [%4];"
                 : "=r"(r[0]), "=r"(r[1]), "=r"(r[2]), "=r"(r[3]) : "r"(a));
}
__device__ __forceinline__ void ldm_x4_t(uint32_t* r, uint32_t a) {
    asm volatile("ldmatrix.sync.aligned.m8n8.x4.trans.shared.b16 {%0,%1,%2,%3}, [%4];"
                 : "=r"(r[0]), "=r"(r[1]), "=r"(r[2]), "=r"(r[3]) : "r"(a));
}
__device__ __forceinline__ void mma_f16(float* c, const uint32_t* a, const uint32_t* b) {
    asm volatile("mma.sync.aligned.m16n8k16.row.col.f32.f16.f16.f32 "
                 "{%0,%1,%2,%3}, {%4,%5,%6,%7}, {%8,%9}, {%0,%1,%2,%3};"
                 : "+f"(c[0]), "+f"(c[1]), "+f"(c[2]), "+f"(c[3])
                 : "r"(a[0]), "r"(a[1]), "r"(a[2]), "r"(a[3]), "r"(b[0]), "r"(b[1]));
}
// packed fp16 exp2: input f16x2, output f16x2 (one MUFU op for two values)
__device__ __forceinline__ uint32_t ex2_f16x2(uint32_t x) {
    uint32_t y; asm("ex2.approx.f16x2 %0, %1;" : "=r"(y) : "r"(x)); return y;
}
// pack two fp32 -> fp16x2; second arg lands in the LOW half
__device__ __forceinline__ uint32_t cvt_f16x2(float hi, float lo) {
    uint32_t r; asm("cvt.rn.f16x2.f32 %0, %1, %2;" : "=r"(r) : "f"(hi), "f"(lo)); return r;
}
__device__ __forceinline__ uint32_t lds32(uint32_t a) {
    uint32_t v; asm volatile("ld.shared.b32 %0, [%1];" : "=r"(v) : "r"(a)); return v;
}
__device__ __forceinline__ void sts128(uint32_t a, uint32_t x, uint32_t y, uint32_t z, uint32_t w) {
    asm volatile("st.shared.v4.b32 [%0], {%1,%2,%3,%4};"
                 :: "r"(a), "r"(x), "r"(y), "r"(z), "r"(w) : "memory");
}
__device__ __forceinline__ void cpa16(uint32_t dst, const void* src) {
    asm volatile("cp.async.cg.shared.global [%0], [%1], 16;" :: "r"(dst), "l"(src));
}
#define CP_COMMIT() asm volatile("cp.async.commit_group;" ::: "memory")
#define CP_WAIT0()  asm volatile("cp.async.wait_group 0;" ::: "memory")

// ---------------------------------------------------------------------------
// Kernel 1: tensor-core QKV projection (round-13 measured-best; no prefetch).
// D = E @ W^T emulated in fp32 precision by fp16 hi/lo (3 combos).
// Also: pad dtype detect + canonical half mask, padded-K/V zeroing, and
// per-CTA fp32 V_p column sums (meanV). 128 CTAs x 256 threads.
// ---------------------------------------------------------------------------
constexpr int PSE_HI = 0;                       // E hi: 128 x 128B (swizzled)
constexpr int PSE_LO = 16384;                   // E lo
constexpr int PSW    = 32768;                   // W: 3 x (hi 8KB + lo 8KB)
constexpr int PROJ_SMEM = PSW + 3 * 16384;      // 81920

__global__ __launch_bounds__(256) void proj_kernel(
    const float* __restrict__ E,  const float* __restrict__ PK, const float* __restrict__ PV,
    const float* __restrict__ Wq, const float* __restrict__ bq,
    const float* __restrict__ Wk, const float* __restrict__ bk,
    const float* __restrict__ Wv, const float* __restrict__ bv,
    const void* __restrict__ pad)
{
    extern __shared__ char psm[];
    const uint32_t smb = smem_u32(psm);
    __shared__ float bsm[3][64];
    __shared__ float keepf[128];
    __shared__ float comb[128];
    __shared__ int f[2];
    const int t = threadIdx.x, wid = t >> 5, lane = t & 31;
    const int g8 = lane >> 3, l8 = lane & 7, l4 = lane >> 2, lq = lane & 3;
    const int bid = blockIdx.x;

    if (t < 2) f[t] = 0;
    if (t < 64) { bsm[0][t] = bq[t]; bsm[1][t] = bk[t]; bsm[2][t] = bv[t]; }

    // ---- stage E hi/lo (row = t>>1, half-row of 32 floats per thread) ----
    {
        const int row = t >> 1, half = t & 1;
        const float4* er = reinterpret_cast<const float4*>(
            E + ((size_t)bid * 128 + row) * 64 + half * 32);
        #pragma unroll
        for (int k = 0; k < 4; k++) {
            float4 va = er[2 * k], vb = er[2 * k + 1];
            float v[8] = {va.x, va.y, va.z, va.w, vb.x, vb.y, vb.z, vb.w};
            uint32_t uh[4], ul[4];
            #pragma unroll
            for (int j = 0; j < 4; j++) {
                const __half h0 = __float2half_rn(v[2*j]);
                const __half h1 = __float2half_rn(v[2*j+1]);
                const __half e0 = __float2half_rn(v[2*j]   - __half2float(h0));
                const __half e1 = __float2half_rn(v[2*j+1] - __half2float(h1));
                uh[j] = (uint32_t)__half_as_ushort(h0) | ((uint32_t)__half_as_ushort(h1) << 16);
                ul[j] = (uint32_t)__half_as_ushort(e0) | ((uint32_t)__half_as_ushort(e1) << 16);
            }
            const int c = half * 4 + k;
            const uint32_t sw = (uint32_t)row * 128 + (((uint32_t)(c ^ (row & 7))) << 4);
            sts128(smb + PSE_HI + sw, uh[0], uh[1], uh[2], uh[3]);
            sts128(smb + PSE_LO + sw, ul[0], ul[1], ul[2], ul[3]);
        }
    }

    // ---- stage W hi/lo (3 matrices x 64 rows x 2 half-rows = 384 units) ----
    {
        const float* Wsrc[3] = {Wq, Wk, Wv};
        #pragma unroll
        for (int u = t; u < 384; u += 256) {
            const int m = u >> 7, rem = u & 127, row = rem >> 1, half = rem & 1;
            const float4* wr4 = reinterpret_cast<const float4*>(Wsrc[m] + row * 64 + half * 32);
            #pragma unroll
            for (int k = 0; k < 4; k++) {
                float4 va = wr4[2 * k], vb = wr4[2 * k + 1];
                float v[8] = {va.x, va.y, va.z, va.w, vb.x, vb.y, vb.z, vb.w};
                uint32_t uh[4], ul[4];
                #pragma unroll
                for (int j = 0; j < 4; j++) {
                    const __half h0 = __float2half_rn(v[2*j]);
                    const __half h1 = __float2half_rn(v[2*j+1]);
                    const __half e0 = __float2half_rn(v[2*j]   - __half2float(h0));
                    const __half e1 = __float2half_rn(v[2*j+1] - __half2float(h1));
                    uh[j] = (uint32_t)__half_as_ushort(h0) | ((uint32_t)__half_as_ushort(h1) << 16);
                    ul[j] = (uint32_t)__half_as_ushort(e0) | ((uint32_t)__half_as_ushort(e1) << 16);
                }
                const int c = half * 4 + k;
                const uint32_t sw = (uint32_t)row * 128 + (((uint32_t)(c ^ (row & 7))) << 4);
                const uint32_t base = smb + PSW + m * 16384;
                sts128(base + sw, uh[0], uh[1], uh[2], uh[3]);
                sts128(base + 8192 + sw, ul[0], ul[1], ul[2], ul[3]);
            }
        }
    }

    // ---- pad dtype detection (16KB scan = minimum buffer size) ----
    {
        const uint4* p4 = reinterpret_cast<const uint4*>(pad);
        uint32_t ge2 = 0, odd = 0;
        #pragma unroll
        for (int i = t; i < 1024; i += 256) {
            uint4 v = p4[i];
            uint32_t o = v.x | v.y | v.z | v.w;
            ge2 |= o & 0xFEFEFEFEu;
            odd |= o & 0xFFFFFF00u;
        }
        if (ge2) atomicOr(&f[0], 1);
        if (odd) atomicOr(&f[1], 1);
    }
    __syncthreads();

    // ---- canonical half mask + keep flags for this CTA's 128 rows ----
    if (t < 128) {
        const int kind = f[0] ? 2 : (f[1] ? 0 : 1);   // 0=u8, 1=i32, 2=f32
        const int i = bid * 128 + t;
        bool m;
        if (kind == 0)      m = ((const unsigned char*)pad)[i] != 0;
        else if (kind == 1) m = ((const int*)pad)[i] != 0;
        else                m = ((const float*)pad)[i] != 0.f;
        const float k = m ? 0.f : 1.f;
        keepf[t] = k;
        g_pad1h[i] = __float2half(k);
    }
    __syncthreads();

    // ---- A fragments (E rows, hi/lo), 4 k-chunks of 16 ----
    uint32_t ah[4][4], al[4][4];
    {
        const int arow = wid * 16 + (g8 & 1) * 8 + l8;
        #pragma unroll
        for (int dc = 0; dc < 4; dc++) {
            const int c = 2 * dc + (g8 >> 1);
            const uint32_t a0 = smb + PSE_HI + arow * 128 + (((uint32_t)(c ^ (arow & 7))) << 4);
            ldm_x4(ah[dc], a0);
            ldm_x4(al[dc], a0 + (PSE_LO - PSE_HI));
        }
    }
    __syncthreads();   // all A-frag reads done before red overlays the E area

    const int r0l = wid * 16 + l4;                 // local rows r0l, r0l+8
    const size_t grow0 = (size_t)bid * 128 + r0l;
    const float keep0 = keepf[r0l], keep1 = keepf[r0l + 8];
    float* red = reinterpret_cast<float*>(psm + PSE_HI);   // 128 x 64 fp32 overlay

    __half* gdsts[3] = {g_Qh, g_Kh, g_Vh};

    #pragma unroll 1
    for (int m = 0; m < 3; m++) {
        float C[8][4];
        #pragma unroll
        for (int i = 0; i < 8; i++)
            { C[i][0] = 0.f; C[i][1] = 0.f; C[i][2] = 0.f; C[i][3] = 0.f; }
        const uint32_t wb = smb + PSW + m * 16384;

        #pragma unroll
        for (int nb = 0; nb < 4; nb++) {
            #pragma unroll
            for (int ks = 0; ks < 4; ks++) {
                const int row = nb * 16 + (g8 >> 1) * 8 + l8;
                const int c = 2 * ks + (g8 & 1);
                const uint32_t a = wb + row * 128 + (((uint32_t)(c ^ (row & 7))) << 4);
                uint32_t bh[4], bl[4];
                ldm_x4(bh, a);
                ldm_x4(bl, a + 8192);
                mma_f16(C[2*nb],   ah[ks], bh);
                mma_f16(C[2*nb],   al[ks], bh);
                mma_f16(C[2*nb],   ah[ks], bl);
                mma_f16(C[2*nb+1], ah[ks], bh + 2);
                mma_f16(C[2*nb+1], al[ks], bh + 2);
                mma_f16(C[2*nb+1], ah[ks], bl + 2);
            }
        }

        // ---- epilogue: bias + scale/modulate + keep-zero + fp16 store ----
        __half* gd = gdsts[m];
        #pragma unroll
        for (int i = 0; i < 8; i++) {
            const int c0 = i * 8 + 2 * lq;
            const float b0 = bsm[m][c0], b1 = bsm[m][c0 + 1];
            float v00 = C[i][0] + b0, v01 = C[i][1] + b1;
            float v10 = C[i][2] + b0, v11 = C[i][3] + b1;
            if (m == 0) {
                v00 *= QSCALE; v01 *= QSCALE; v10 *= QSCALE; v11 *= QSCALE;
            } else {
                const float* mod = (m == 1 ? PK : PV);
                const float2 m0 = *reinterpret_cast<const float2*>(mod + grow0 * 64 + c0);
                const float2 m1 = *reinterpret_cast<const float2*>(mod + (grow0 + 8) * 64 + c0);
                v00 *= m0.x; v01 *= m0.y; v10 *= m1.x; v11 *= m1.y;
                if (m == 2) {   // stash UN-zeroed fp32 V_p for meanV
                    *reinterpret_cast<float2*>(&red[r0l * 64 + c0])       = make_float2(v00, v01);
                    *reinterpret_cast<float2*>(&red[(r0l + 8) * 64 + c0]) = make_float2(v10, v11);
                }
                v00 *= keep0; v01 *= keep0; v10 *= keep1; v11 *= keep1;
            }
            *reinterpret_cast<uint32_t*>(&gd[grow0 * 64 + c0])       = cvt_f16x2(v01, v00);
            *reinterpret_cast<uint32_t*>(&gd[(grow0 + 8) * 64 + c0]) = cvt_f16x2(v11, v10);
        }
    }

    // ---- meanV partial for this CTA's 128 rows ----
    __syncthreads();
    if (t < 128) {
        const int col = t & 63, half = t >> 6;
        float a = 0.f;
        #pragma unroll 8
        for (int r = half * 64; r < half * 64 + 64; r++) a += red[r * 64 + col];
        comb[t] = a;
    }
    __syncthreads();
    if (t < 64) g_part[bid][t] = comb[t] + comb[t + 64];
}

// ---------------------------------------------------------------------------
// Kernel 2: single-fp16 mma.sync flash attention, cp.async double-buffered.
// CTA = 256 threads = 2 row-groups (32 q-rows) x 4 key-quarters (64 keys).
// NT=256 keys/tile: exactly 17 tiles per CTA for every pair (qt, 63-qt)
// (floor(qt/4)+floor((63-qt)/4)=15 identity), halving barrier count.
// Warp-uniform chunk skipping recovers masked diagonal-tile work.
// Softmax exp via packed ex2.approx.f16x2; padding folded into the GEMMs.
// ---------------------------------------------------------------------------
constexpr int SM_QH   = 0;                      // 64 x 128B
constexpr int SM_KV   = 8192;                   // 2 stages x (K 32KB + V 32KB)
constexpr int STG_SZ  = 65536;
constexpr int OFF_K   = 0, OFF_V = 32768;
constexpr int SM_PADB = SM_KV + 2 * STG_SZ;     // 139264, 2 x 512B (half mask)
constexpr int SM_LSM  = SM_PADB + 1024;         // 140288, 4 x 64 f32
constexpr int SM_MNV  = SM_LSM + 1024;          // 141312, 64 f32
constexpr int SM_MRG  = SM_KV;                  // merge overlays stages (drained)
constexpr int SM_TOTAL = SM_MNV + 256;          // 141568

// One k-tile body with compile-time stage STc (0/1).
#define TILE_BODY(STc, J)                                                      \
do {                                                                           \
    const int kt_ = (J) * NT;                                                  \
    const uint32_t stb_  = smb + (uint32_t)(SM_KV + (STc) * STG_SZ);           \
    const uint32_t padb_ = smb + (uint32_t)(SM_PADB + (STc) * 512);            \
    if ((J) + 1 < nkt) {                                                       \
        const int ktn_ = ((J) + 1) * NT;                                       \
        const uint32_t nstb_ = smb + (uint32_t)(SM_KV + (1 - (STc)) * STG_SZ); \
        const __half* srcK_ = g_Kh + ((size_t)b * S_ + ktn_) * D_;             \
        const __half* srcV_ = g_Vh + ((size_t)b * S_ + ktn_) * D_;             \
        _Pragma("unroll")                                                      \
        for (int it = 0; it < 8; it++) {                                       \
            const int i = tid + it * 256;                                      \
            const int row = i >> 3, c = i & 7;                                 \
            const uint32_t off = (uint32_t)row * 128 +                         \
                                 (((uint32_t)(c ^ (row & 7))) << 4);           \
            cpa16(nstb_ + off,         reinterpret_cast<const uint4*>(srcK_) + i); \
            cpa16(nstb_ + 32768 + off, reinterpret_cast<const uint4*>(srcV_) + i); \
        }                                                                      \
        if (tid < 32)                                                          \
            cpa16(smb + (uint32_t)(SM_PADB + (1 - (STc)) * 512) + tid * 16,    \
                  (const char*)(g_pad1h + b * S_ + ktn_) + tid * 16);          \
        CP_COMMIT();                                                           \
    }                                                                          \
    const bool interior_ = ((J) < nkt - 1);                                    \
    _Pragma("unroll")                                                          \
    for (int kp = 0; kp < 4; kp++) {                                           \
        if (interior_ || kt_ + kb0 + kp * 16 <= qmax) {                        \
            float SC[2][2][4];                                                 \
            _Pragma("unroll")                                                  \
            for (int rc = 0; rc < 2; rc++)                                     \
                _Pragma("unroll")                                              \
                for (int n = 0; n < 2; n++)                                    \
                    { SC[rc][n][0]=0.f; SC[rc][n][1]=0.f; SC[rc][n][2]=0.f; SC[rc][n][3]=0.f; } \
            {                                                                  \
                const int krow = kb0 + kp * 16 + (g8 >> 1) * 8 + l8;           \
                _Pragma("unroll")                                              \
                for (int dc = 0; dc < 4; dc++) {                               \
                    const int c = 2 * dc + (g8 & 1);                           \
                    uint32_t bh[4];                                            \
                    ldm_x4(bh, stb_ + OFF_K + krow * 128 +                     \
                               (((uint32_t)(c ^ (krow & 7))) << 4));           \
                    _Pragma("unroll")                                          \
                    for (int rc = 0; rc < 2; rc++) {                           \
                        mma_f16(SC[rc][0], qh[rc][dc], bh);                    \
                        mma_f16(SC[rc][1], qh[rc][dc], bh + 2);                \
                    }                                                          \
                }                                                              \
            }                                                                  \
            uint32_t Ph[2][4];                                                 \
            if (interior_) {                                                   \
                _Pragma("unroll")                                              \
                for (int rc = 0; rc < 2; rc++)                                 \
                    _Pragma("unroll")                                          \
                    for (int n = 0; n < 2; n++) {                              \
                        Ph[rc][n * 2]     = ex2_f16x2(cvt_f16x2(SC[rc][n][1], SC[rc][n][0])); \
                        Ph[rc][n * 2 + 1] = ex2_f16x2(cvt_f16x2(SC[rc][n][3], SC[rc][n][2])); \
                    }                                                          \
            } else {                                                           \
                _Pragma("unroll")                                              \
                for (int rc = 0; rc < 2; rc++) {                               \
                    const int qr0 = qbase + rg * 32 + rc * 16 + l4;            \
                    const int qr1 = qr0 + 8;                                   \
                    _Pragma("unroll")                                          \
                    for (int n = 0; n < 2; n++) {                              \
                        const int key = kt_ + kb0 + kp * 16 + n * 8 + 2 * lq;  \
                        const uint32_t mA = (key <= qr0 ? 0xFFFFu : 0u) |      \
                                            (key + 1 <= qr0 ? 0xFFFF0000u : 0u); \
                        const uint32_t mB = (key <= qr1 ? 0xFFFFu : 0u) |      \
                                            (key + 1 <= qr1 ? 0xFFFF0000u : 0u); \
                        Ph[rc][n * 2]     = ex2_f16x2(cvt_f16x2(SC[rc][n][1], SC[rc][n][0])) & mA; \
                        Ph[rc][n * 2 + 1] = ex2_f16x2(cvt_f16x2(SC[rc][n][3], SC[rc][n][2])) & mB; \
                    }                                                          \
                }                                                              \
            }                                                                  \
            {                                                                  \
                const uint32_t a = padb_ + (uint32_t)(kb0 + kp * 16 + 2 * lq) * 2; \
                uint32_t bm[2];                                                \
                bm[0] = lds32(a);                                              \
                bm[1] = lds32(a + 16);                                         \
                _Pragma("unroll")                                              \
                for (int rc = 0; rc < 2; rc++) mma_f16(LM[rc], Ph[rc], bm);    \
            }                                                                  \
            {                                                                  \
                const int vrow = kb0 + kp * 16 + (g8 & 1) * 8 + l8;            \
                _Pragma("unroll")                                              \
                for (int ndp = 0; ndp < 4; ndp++) {                            \
                    const int c = 2 * ndp + (g8 >> 1);                         \
                    uint32_t bh[4];                                            \
                    ldm_x4_t(bh, stb_ + OFF_V + vrow * 128 +                   \
                                 (((uint32_t)(c ^ (vrow & 7))) << 4));         \
                    _Pragma("unroll")                                          \
                    for (int rc = 0; rc < 2; rc++) {                           \
                        mma_f16(OC[rc][2*ndp],   Ph[rc], bh);                  \
                        mma_f16(OC[rc][2*ndp+1], Ph[rc], bh + 2);              \
                    }                                                          \
                }                                                              \
            }                                                                  \
        }                                                                      \
    }                                                                          \
    if ((J) + 1 < nkt) CP_WAIT0();                                             \
    __syncthreads();                                                           \
} while (0)

__global__ __launch_bounds__(256, 1) void attn_mma_kernel(float* __restrict__ out)
{
    extern __shared__ char sm[];
    const uint32_t smb = smem_u32(sm);
    const int tid = threadIdx.x, wid = tid >> 5, lane = tid & 31;
    const int rg = wid & 1, wc = wid >> 1;        // row-group (0..1), key-quarter (0..3)
    const int b = blockIdx.y;
    const int g8 = lane >> 3, l8 = lane & 7, l4 = lane >> 2, lq = lane & 3;
    float* lsm  = reinterpret_cast<float*>(sm + SM_LSM);
    float* mnv  = reinterpret_cast<float*>(sm + SM_MNV);
    float* mrg  = reinterpret_cast<float*>(sm + SM_MRG);

    // ---- meanV for this batch (sum of 32 proj-CTA partials) ----
    if (tid < 64) {
        float a = 0.f;
        #pragma unroll 8
        for (int i = 0; i < 32; i++) a += g_part[b * 32 + i][tid];
        mnv[tid] = a * (1.0f / (float)S_);
    }

    #pragma unroll 1
    for (int phase = 0; phase < 2; phase++) {
        const int qt = phase ? (63 - blockIdx.x) : blockIdx.x;
        const int qbase = qt * MT;
        const int qmax = qbase + 63;
        const int nkt = (qt >> 2) + 1;

        __syncthreads();   // prev phase merge reads done (and mnv visible)

        // ---- prologue: async-copy Q + k-tile 0 into stage 0 ----
        {
            const uint4* qh4 = reinterpret_cast<const uint4*>(g_Qh + ((size_t)b * S_ + qbase) * D_);
            #pragma unroll
            for (int it = 0; it < 2; it++) {
                int i = tid + it * 256;
                int row = i >> 3, c = i & 7;
                uint32_t sw = row * 128 + (((uint32_t)(c ^ (row & 7))) << 4);
                cpa16(smb + SM_QH + sw, qh4 + i);
            }
            const __half* srcK = g_Kh + (size_t)b * S_ * D_;
            const __half* srcV = g_Vh + (size_t)b * S_ * D_;
            #pragma unroll
            for (int it = 0; it < 8; it++) {
                int i = tid + it * 256;
                int row = i >> 3, c = i & 7;
                uint32_t off = (uint32_t)row * 128 + (((uint32_t)(c ^ (row & 7))) << 4);
                cpa16(smb + SM_KV + off,         reinterpret_cast<const uint4*>(srcK) + i);
                cpa16(smb + SM_KV + 32768 + off, reinterpret_cast<const uint4*>(srcV) + i);
            }
            if (tid < 32)
                cpa16(smb + SM_PADB + tid * 16, (const char*)(g_pad1h + b * S_) + tid * 16);
            CP_COMMIT();
        }
        CP_WAIT0();
        __syncthreads();

        // ---- Q A-fragments: 2 row-chunks x 4 d-chunks ----
        uint32_t qh[2][4][4];
        #pragma unroll
        for (int rc = 0; rc < 2; rc++) {
            const int row = rg * 32 + rc * 16 + (g8 & 1) * 8 + l8;
            #pragma unroll
            for (int dc = 0; dc < 4; dc++) {
                const int c = 2 * dc + (g8 >> 1);
                ldm_x4(qh[rc][dc], smb + SM_QH + row * 128 + (((uint32_t)(c ^ (row & 7))) << 4));
            }
        }

        float OC[2][8][4];
        #pragma unroll
        for (int rc = 0; rc < 2; rc++)
            #pragma unroll
            for (int i = 0; i < 8; i++)
                { OC[rc][i][0] = 0.f; OC[rc][i][1] = 0.f; OC[rc][i][2] = 0.f; OC[rc][i][3] = 0.f; }
        float LM[2][4] = {{0.f,0.f,0.f,0.f},{0.f,0.f,0.f,0.f}};
        const int kb0 = wc * 64;

        // ---- k-tile loop, unrolled by 2 with compile-time stages ----
        #pragma unroll 1
        for (int jj = 0; jj < nkt; jj += 2) {
            TILE_BODY(0, jj);
            if (jj + 1 < nkt) TILE_BODY(1, jj + 1);
        }

        // ---- merge the four key-quarters (ADD; no rescaling needed) ----
        if (lq == 0) {
            #pragma unroll
            for (int rc = 0; rc < 2; rc++) {
                lsm[wc * 64 + rg * 32 + rc * 16 + l4]     = LM[rc][0];
                lsm[wc * 64 + rg * 32 + rc * 16 + 8 + l4] = LM[rc][2];
            }
        }
        if (wc != 0) {
            float* mq = mrg + (wc - 1) * 4096;
            #pragma unroll
            for (int rc = 0; rc < 2; rc++) {
                const int r0 = rg * 32 + rc * 16 + l4;
                #pragma unroll
                for (int nd = 0; nd < 8; nd++) {
                    const int d0 = nd * 8 + 2 * lq;
                    *reinterpret_cast<float2*>(&mq[r0 * 64 + d0]) =
                        make_float2(OC[rc][nd][0], OC[rc][nd][1]);
                    *reinterpret_cast<float2*>(&mq[(r0 + 8) * 64 + d0]) =
                        make_float2(OC[rc][nd][2], OC[rc][nd][3]);
                }
            }
        }
        __syncthreads();
        if (wc == 0) {
            #pragma unroll
            for (int rc = 0; rc < 2; rc++) {
                const int r0 = rg * 32 + rc * 16 + l4;
                const float lt0 = lsm[r0] + lsm[64 + r0] + lsm[128 + r0] + lsm[192 + r0];
                const float lt1 = lsm[r0 + 8] + lsm[64 + r0 + 8] + lsm[128 + r0 + 8] + lsm[192 + r0 + 8];
                const bool am0 = (lt0 == 0.f), am1 = (lt1 == 0.f);
                const float inv0 = am0 ? 0.f : 1.f / lt0;
                const float inv1 = am1 ? 0.f : 1.f / lt1;
                const int qr0 = qbase + r0, qr1 = qr0 + 8;
                #pragma unroll
                for (int nd = 0; nd < 8; nd++) {
                    const int d0 = nd * 8 + 2 * lq;
                    float a0 = OC[rc][nd][0], a1 = OC[rc][nd][1];
                    float a2 = OC[rc][nd][2], a3 = OC[rc][nd][3];
                    #pragma unroll
                    for (int qq = 0; qq < 3; qq++) {
                        const float* mq = mrg + qq * 4096;
                        const float2 m0v = *reinterpret_cast<const float2*>(&mq[r0 * 64 + d0]);
                        const float2 m1v = *reinterpret_cast<const float2*>(&mq[(r0 + 8) * 64 + d0]);
                        a0 += m0v.x; a1 += m0v.y; a2 += m1v.x; a3 += m1v.y;
                    }
                    float2 o0, o1;
                    if (am0) o0 = make_float2(mnv[d0], mnv[d0 + 1]);
                    else     o0 = make_float2(a0 * inv0, a1 * inv0);
                    if (am1) o1 = make_float2(mnv[d0], mnv[d0 + 1]);
                    else     o1 = make_float2(a2 * inv1, a3 * inv1);
                    *reinterpret_cast<float2*>(&out[((size_t)b * S_ + qr0) * D_ + d0]) = o0;
                    *reinterpret_cast<float2*>(&out[((size_t)b * S_ + qr1) * D_ + d0]) = o1;
                }
            }
        }
    }
}

// ---------------------------------------------------------------------------
extern "C" void kernel_launch(void* const* d_in, const int* in_sizes, int n_in,
                              void* d_out, int out_size)
{
    const float* E  = (const float*)d_in[0];
    const float* PK = (const float*)d_in[1];
    const float* PV = (const float*)d_in[2];
    const float* Wq = (const float*)d_in[3];
    const float* bq = (const float*)d_in[4];
    const float* Wk = (const float*)d_in[5];
    const float* bk = (const float*)d_in[6];
    const float* Wv = (const float*)d_in[7];
    const float* bv = (const float*)d_in[8];
    const void*  pad = d_in[9];
    float* out = (float*)d_out;

    cudaFuncSetAttribute(proj_kernel, cudaFuncAttributeMaxDynamicSharedMemorySize, PROJ_SMEM);
    cudaFuncSetAttribute(attn_mma_kernel, cudaFuncAttributeMaxDynamicSharedMemorySize, SM_TOTAL);

    proj_kernel<<<128, 256, PROJ_SMEM>>>(E, PK, PV, Wq, bq, Wk, bk, Wv, bv, pad);
    attn_mma_kernel<<<dim3(32, B_), 256, SM_TOTAL>>>(out);
}